// round 9
// baseline (speedup 1.0000x reference)
#include <cuda_runtime.h>
#include <cuda_bf16.h>
#include <cuda_fp16.h>
#include <cstdint>
#include <cstddef>

#define BDIM 16384
#define ADIM 512
#define MDIM 1024
#define INV_TAU 10.0f

constexpr int BM = 128, BN = 128, BK = 32;
constexpr int PLANE_B = 128 * 64;        // 8 KB: 128 rows x 32 elems x 2B
// drive kernel (bf16x3): 4 planes/stage, double buffered
constexpr int STAGE4_B = 4 * PLANE_B;
constexpr int SMEM_DRIVE = 2 * STAGE4_B;   // 64 KB
// settle kernel (fp16x2): 3 planes/stage (A_hi, A_lo, B_hi), double buffered
constexpr int STAGE3_B = 3 * PLANE_B;
constexpr int SMEM_SETTLE = 2 * STAGE3_B;  // 48 KB

// ---- device scratch (allocation-free rule: __device__ globals) ----
__device__ __align__(128) __nv_bfloat16 g_xh[(size_t)BDIM * MDIM];
__device__ __align__(128) __nv_bfloat16 g_xl[(size_t)BDIM * MDIM];
__device__ __align__(128) __nv_bfloat16 g_wh[(size_t)ADIM * MDIM];
__device__ __align__(128) __nv_bfloat16 g_wl[(size_t)ADIM * MDIM];
__device__ __align__(128) __half g_jh[(size_t)ADIM * ADIM];   // fp16 truncation of J
__device__ __align__(128) float g_drive[(size_t)BDIM * ADIM];
__device__ __align__(128) __half g_sh0[(size_t)BDIM * ADIM];
__device__ __align__(128) __half g_sl0[(size_t)BDIM * ADIM];
__device__ __align__(128) __half g_sh1[(size_t)BDIM * ADIM];
__device__ __align__(128) __half g_sl1[(size_t)BDIM * ADIM];

// ---- helpers ----
__device__ __forceinline__ void cp16(void* sdst, const void* gsrc) {
    uint32_t s = (uint32_t)__cvta_generic_to_shared(sdst);
    asm volatile("cp.async.cg.shared.global [%0], [%1], 16;\n" ::"r"(s), "l"(gsrc));
}

__device__ __forceinline__ void ldsm4(uint32_t* r, const void* p) {
    uint32_t a = (uint32_t)__cvta_generic_to_shared(p);
    asm volatile("ldmatrix.sync.aligned.m8n8.x4.shared.b16 {%0,%1,%2,%3}, [%4];\n"
                 : "=r"(r[0]), "=r"(r[1]), "=r"(r[2]), "=r"(r[3])
                 : "r"(a));
}

__device__ __forceinline__ void mma_bf16(float* c, const uint32_t* a, const uint32_t* b) {
    asm volatile(
        "mma.sync.aligned.m16n8k16.row.col.f32.bf16.bf16.f32 "
        "{%0,%1,%2,%3}, {%4,%5,%6,%7}, {%8,%9}, {%0,%1,%2,%3};\n"
        : "+f"(c[0]), "+f"(c[1]), "+f"(c[2]), "+f"(c[3])
        : "r"(a[0]), "r"(a[1]), "r"(a[2]), "r"(a[3]), "r"(b[0]), "r"(b[1]));
}

__device__ __forceinline__ void mma_fp16(float* c, const uint32_t* a, const uint32_t* b) {
    asm volatile(
        "mma.sync.aligned.m16n8k16.row.col.f32.f16.f16.f32 "
        "{%0,%1,%2,%3}, {%4,%5,%6,%7}, {%8,%9}, {%0,%1,%2,%3};\n"
        : "+f"(c[0]), "+f"(c[1]), "+f"(c[2]), "+f"(c[3])
        : "r"(a[0]), "r"(a[1]), "r"(a[2]), "r"(a[3]), "r"(b[0]), "r"(b[1]));
}

// byte offset inside one smem plane for (row, 16B-chunk): conflict-free for
// cp.async STS phases and all LDSM phases.
__device__ __forceinline__ uint32_t swz(int r, int ch) {
    return (uint32_t)(r * 64 + ((ch ^ ((r >> 1) & 3)) << 4));
}

__device__ __forceinline__ float fast_tanh(float x) {
    float e, r;
    asm("ex2.approx.f32 %0, %1;" : "=f"(e) : "f"(x * 2.8853901817f));  // 2*log2(e)*x
    asm("rcp.approx.f32 %0, %1;" : "=f"(r) : "f"(e + 1.0f));
    return fmaf(-2.0f, r, 1.0f);
}

// split into fp16 hi/lo and store packed pairs
__device__ __forceinline__ void store_split_h(__half* hi, __half* lo, uint32_t i,
                                              float a, float b) {
    __half ha = __float2half_rn(a), hb = __float2half_rn(b);
    __half la = __float2half_rn(a - __half2float(ha));
    __half lb = __float2half_rn(b - __half2float(hb));
    *(__half2*)(hi + i) = __halves2half2(ha, hb);
    *(__half2*)(lo + i) = __halves2half2(la, lb);
}

// ---- split fp32 tensor into bf16 hi/lo planes (for x, W) ----
__global__ void split_arr(const float4* __restrict__ src, uint2* __restrict__ hi,
                          uint2* __restrict__ lo, int n4) {
    int i = blockIdx.x * blockDim.x + threadIdx.x;
    if (i >= n4) return;
    float4 v = src[i];
    float f[4] = {v.x, v.y, v.z, v.w};
    uint32_t h[4], l[4];
#pragma unroll
    for (int k = 0; k < 4; k++) {
        __nv_bfloat16 hb = __float2bfloat16_rn(f[k]);
        __nv_bfloat16 lb = __float2bfloat16_rn(f[k] - __bfloat162float(hb));
        h[k] = (uint32_t)__bfloat16_as_ushort(hb);
        l[k] = (uint32_t)__bfloat16_as_ushort(lb);
    }
    hi[i] = make_uint2(h[0] | (h[1] << 16), h[2] | (h[3] << 16));
    lo[i] = make_uint2(l[0] | (l[1] << 16), l[2] | (l[3] << 16));
}

// ---- truncate fp32 -> fp16 (for J) ----
__global__ void trunc_h(const float4* __restrict__ src, uint2* __restrict__ dst, int n4) {
    int i = blockIdx.x * blockDim.x + threadIdx.x;
    if (i >= n4) return;
    float4 v = src[i];
    __half2 a = __halves2half2(__float2half_rn(v.x), __float2half_rn(v.y));
    __half2 b = __halves2half2(__float2half_rn(v.z), __float2half_rn(v.w));
    dst[i] = make_uint2(*(uint32_t*)&a, *(uint32_t*)&b);
}

// ========== drive kernel: bf16x3, KD=1024 ==========
// drive = x@W^T + bias (fp32 out), sigma1 = tanh(drive) -> fp16 hi/lo
__global__ void __launch_bounds__(256, 2)
drive_gemm(const __nv_bfloat16* __restrict__ Ahi, const __nv_bfloat16* __restrict__ Alo,
           const __nv_bfloat16* __restrict__ Bhi, const __nv_bfloat16* __restrict__ Blo,
           const float* __restrict__ bias, float* __restrict__ of32,
           __half* __restrict__ ohi, __half* __restrict__ olo) {
    constexpr int KD = MDIM;
    extern __shared__ char sm[];
    const int tid = threadIdx.x, lane = tid & 31, wid = tid >> 5;
    const int wm = wid & 3, wn = wid >> 2;
    const int rowBase = blockIdx.y * BM, colBase = blockIdx.x * BN;

    float acc[2][8][4];
#pragma unroll
    for (int mi = 0; mi < 2; mi++)
#pragma unroll
        for (int ni = 0; ni < 8; ni++)
#pragma unroll
            for (int q = 0; q < 4; q++) acc[mi][ni][q] = 0.f;

    uint32_t sA[2], gA[2], gB[2];
#pragma unroll
    for (int j = 0; j < 2; j++) {
        int c = tid + j * 256;
        int r = c >> 2, ch = c & 3;
        sA[j] = swz(r, ch);
        gA[j] = (uint32_t)(rowBase + r) * KD + ch * 8;
        gB[j] = (uint32_t)(colBase + r) * KD + ch * 8;
    }

    auto issue = [&](int kt, int s) {
        char* st = sm + s * STAGE4_B;
        const uint32_t kof = kt * BK;
#pragma unroll
        for (int j = 0; j < 2; j++) {
            cp16(st + sA[j], Ahi + gA[j] + kof);
            cp16(st + PLANE_B + sA[j], Alo + gA[j] + kof);
            cp16(st + 2 * PLANE_B + sA[j], Bhi + gB[j] + kof);
            cp16(st + 3 * PLANE_B + sA[j], Blo + gB[j] + kof);
        }
        asm volatile("cp.async.commit_group;\n");
    };

    const int arowl = lane & 15;
    const int browl = ((lane >> 4) << 3) + (lane & 7);
    uint32_t aOff[2][2], bOff[2][4];
#pragma unroll
    for (int k16 = 0; k16 < 2; k16++) {
        const int achunk = k16 * 2 + (lane >> 4);
        const int bchunk = k16 * 2 + ((lane >> 3) & 1);
#pragma unroll
        for (int mi = 0; mi < 2; mi++)
            aOff[k16][mi] = swz(wm * 32 + mi * 16 + arowl, achunk);
#pragma unroll
        for (int g = 0; g < 4; g++)
            bOff[k16][g] = swz(wn * 64 + g * 16 + browl, bchunk);
    }

    constexpr int KT = KD / BK;
    issue(0, 0);

    for (int kt = 0; kt < KT; kt++) {
        const int buf = kt & 1;
        if (kt + 1 < KT) {
            issue(kt + 1, buf ^ 1);
            asm volatile("cp.async.wait_group 1;\n");
        } else {
            asm volatile("cp.async.wait_group 0;\n");
        }
        __syncthreads();
        char* st = sm + buf * STAGE4_B;

#pragma unroll
        for (int k16 = 0; k16 < 2; k16++) {
            uint32_t ah[2][4], al[2][4], bb[4][4];
#pragma unroll
            for (int mi = 0; mi < 2; mi++) {
                ldsm4(ah[mi], st + aOff[k16][mi]);
                ldsm4(al[mi], st + PLANE_B + aOff[k16][mi]);
            }
#pragma unroll
            for (int g = 0; g < 4; g++)
                ldsm4(bb[g], st + 2 * PLANE_B + bOff[k16][g]);
#pragma unroll
            for (int ni = 0; ni < 8; ni++) {
                const uint32_t* b = &bb[ni >> 1][(ni & 1) * 2];
                mma_bf16(acc[0][ni], ah[0], b);
                mma_bf16(acc[1][ni], ah[1], b);
                mma_bf16(acc[0][ni], al[0], b);
                mma_bf16(acc[1][ni], al[1], b);
            }
#pragma unroll
            for (int g = 0; g < 4; g++)
                ldsm4(bb[g], st + 3 * PLANE_B + bOff[k16][g]);
#pragma unroll
            for (int ni = 0; ni < 8; ni++) {
                const uint32_t* b = &bb[ni >> 1][(ni & 1) * 2];
                mma_bf16(acc[0][ni], ah[0], b);
                mma_bf16(acc[1][ni], ah[1], b);
            }
        }
        __syncthreads();
    }

    const int lrow = lane >> 2, lcol = lane & 3;
#pragma unroll
    for (int mi = 0; mi < 2; mi++) {
#pragma unroll
        for (int ni = 0; ni < 8; ni++) {
            const int gr = rowBase + wm * 32 + mi * 16 + lrow;
            const int gc = colBase + wn * 64 + ni * 8 + lcol * 2;
            const uint32_t i0 = (uint32_t)gr * ADIM + gc;
            const uint32_t i1 = i0 + 8 * ADIM;
            const float b0 = bias[gc], b1 = bias[gc + 1];
            float v0 = acc[mi][ni][0] + b0, v1 = acc[mi][ni][1] + b1;
            float v2 = acc[mi][ni][2] + b0, v3 = acc[mi][ni][3] + b1;
            *(float2*)(of32 + i0) = make_float2(v0, v1);
            *(float2*)(of32 + i1) = make_float2(v2, v3);
            store_split_h(ohi, olo, i0, fast_tanh(v0), fast_tanh(v1));
            store_split_h(ohi, olo, i1, fast_tanh(v2), fast_tanh(v3));
        }
    }
}

// ========== settle kernel: fp16x2, KD=512 ==========
// s = tanh(drive + C*INV_TAU), C = sigma @ J^T  (J fp16-truncated; sigma exact via hi+lo)
// MODE 1: store fp16 hi/lo split; MODE 2: store fp32 to of32
template <int MODE>
__global__ void __launch_bounds__(256, 2)
settle_fp16(const __half* __restrict__ Ahi, const __half* __restrict__ Alo,
            const __half* __restrict__ Bh, const float* __restrict__ aux,
            __half* __restrict__ ohi, __half* __restrict__ olo,
            float* __restrict__ of32) {
    constexpr int KD = ADIM;
    extern __shared__ char sm[];
    const int tid = threadIdx.x, lane = tid & 31, wid = tid >> 5;
    const int wm = wid & 3, wn = wid >> 2;
    const int rowBase = blockIdx.y * BM, colBase = blockIdx.x * BN;

    float acc[2][8][4];
#pragma unroll
    for (int mi = 0; mi < 2; mi++)
#pragma unroll
        for (int ni = 0; ni < 8; ni++)
#pragma unroll
            for (int q = 0; q < 4; q++) acc[mi][ni][q] = 0.f;

    uint32_t sA[2], gA[2], gB[2];
#pragma unroll
    for (int j = 0; j < 2; j++) {
        int c = tid + j * 256;
        int r = c >> 2, ch = c & 3;
        sA[j] = swz(r, ch);
        gA[j] = (uint32_t)(rowBase + r) * KD + ch * 8;
        gB[j] = (uint32_t)(colBase + r) * KD + ch * 8;
    }

    auto issue = [&](int kt, int s) {
        char* st = sm + s * STAGE3_B;
        const uint32_t kof = kt * BK;
#pragma unroll
        for (int j = 0; j < 2; j++) {
            cp16(st + sA[j], Ahi + gA[j] + kof);
            cp16(st + PLANE_B + sA[j], Alo + gA[j] + kof);
            cp16(st + 2 * PLANE_B + sA[j], Bh + gB[j] + kof);
        }
        asm volatile("cp.async.commit_group;\n");
    };

    const int arowl = lane & 15;
    const int browl = ((lane >> 4) << 3) + (lane & 7);
    uint32_t aOff[2][2], bOff[2][4];
#pragma unroll
    for (int k16 = 0; k16 < 2; k16++) {
        const int achunk = k16 * 2 + (lane >> 4);
        const int bchunk = k16 * 2 + ((lane >> 3) & 1);
#pragma unroll
        for (int mi = 0; mi < 2; mi++)
            aOff[k16][mi] = swz(wm * 32 + mi * 16 + arowl, achunk);
#pragma unroll
        for (int g = 0; g < 4; g++)
            bOff[k16][g] = swz(wn * 64 + g * 16 + browl, bchunk);
    }

    constexpr int KT = KD / BK;
    issue(0, 0);

    for (int kt = 0; kt < KT; kt++) {
        const int buf = kt & 1;
        if (kt + 1 < KT) {
            issue(kt + 1, buf ^ 1);
            asm volatile("cp.async.wait_group 1;\n");
        } else {
            asm volatile("cp.async.wait_group 0;\n");
        }
        __syncthreads();
        char* st = sm + buf * STAGE3_B;

#pragma unroll
        for (int k16 = 0; k16 < 2; k16++) {
            uint32_t ah[2][4], al[2][4], bb[4][4];
#pragma unroll
            for (int mi = 0; mi < 2; mi++) {
                ldsm4(ah[mi], st + aOff[k16][mi]);
                ldsm4(al[mi], st + PLANE_B + aOff[k16][mi]);
            }
#pragma unroll
            for (int g = 0; g < 4; g++)
                ldsm4(bb[g], st + 2 * PLANE_B + bOff[k16][g]);
            // pass 1: hi * B ; pass 2: lo * B   => (hi+lo)=exact sigma times fp16(J)
#pragma unroll
            for (int ni = 0; ni < 8; ni++) {
                const uint32_t* b = &bb[ni >> 1][(ni & 1) * 2];
                mma_fp16(acc[0][ni], ah[0], b);
                mma_fp16(acc[1][ni], ah[1], b);
                mma_fp16(acc[0][ni], al[0], b);
                mma_fp16(acc[1][ni], al[1], b);
            }
        }
        __syncthreads();
    }

    const int lrow = lane >> 2, lcol = lane & 3;
#pragma unroll
    for (int mi = 0; mi < 2; mi++) {
#pragma unroll
        for (int ni = 0; ni < 8; ni++) {
            const int gr = rowBase + wm * 32 + mi * 16 + lrow;
            const int gc = colBase + wn * 64 + ni * 8 + lcol * 2;
            const uint32_t i0 = (uint32_t)gr * ADIM + gc;
            const uint32_t i1 = i0 + 8 * ADIM;
            const float2 d0 = *(const float2*)(aux + i0);
            const float2 d1 = *(const float2*)(aux + i1);
            float v0 = fast_tanh(fmaf(acc[mi][ni][0], INV_TAU, d0.x));
            float v1 = fast_tanh(fmaf(acc[mi][ni][1], INV_TAU, d0.y));
            float v2 = fast_tanh(fmaf(acc[mi][ni][2], INV_TAU, d1.x));
            float v3 = fast_tanh(fmaf(acc[mi][ni][3], INV_TAU, d1.y));
            if (MODE == 1) {
                store_split_h(ohi, olo, i0, v0, v1);
                store_split_h(ohi, olo, i1, v2, v3);
            } else {
                *(float2*)(of32 + i0) = make_float2(v0, v1);
                *(float2*)(of32 + i1) = make_float2(v2, v3);
            }
        }
    }
}

extern "C" void kernel_launch(void* const* d_in, const int* in_sizes, int n_in,
                              void* d_out, int out_size) {
    (void)in_sizes; (void)n_in; (void)out_size;
    const float* x = (const float*)d_in[0];  // [16384, 1024]
    const float* W = (const float*)d_in[1];  // [512, 1024]
    const float* b = (const float*)d_in[2];  // [512]
    const float* J = (const float*)d_in[3];  // [512, 512]
    float* out = (float*)d_out;              // [16384, 512]

    cudaFuncSetAttribute((const void*)drive_gemm,
                         cudaFuncAttributeMaxDynamicSharedMemorySize, SMEM_DRIVE);
    cudaFuncSetAttribute((const void*)settle_fp16<1>,
                         cudaFuncAttributeMaxDynamicSharedMemorySize, SMEM_SETTLE);
    cudaFuncSetAttribute((const void*)settle_fp16<2>,
                         cudaFuncAttributeMaxDynamicSharedMemorySize, SMEM_SETTLE);

    __nv_bfloat16 *xh, *xl, *wh, *wl;
    __half *jh, *sh0, *sl0, *sh1, *sl1;
    float* drv;
    cudaGetSymbolAddress((void**)&xh, g_xh);
    cudaGetSymbolAddress((void**)&xl, g_xl);
    cudaGetSymbolAddress((void**)&wh, g_wh);
    cudaGetSymbolAddress((void**)&wl, g_wl);
    cudaGetSymbolAddress((void**)&jh, g_jh);
    cudaGetSymbolAddress((void**)&sh0, g_sh0);
    cudaGetSymbolAddress((void**)&sl0, g_sl0);
    cudaGetSymbolAddress((void**)&sh1, g_sh1);
    cudaGetSymbolAddress((void**)&sl1, g_sl1);
    cudaGetSymbolAddress((void**)&drv, g_drive);

    {
        int n4 = BDIM * MDIM / 4;
        split_arr<<<(n4 + 255) / 256, 256>>>((const float4*)x, (uint2*)xh, (uint2*)xl, n4);
        n4 = ADIM * MDIM / 4;
        split_arr<<<(n4 + 255) / 256, 256>>>((const float4*)W, (uint2*)wh, (uint2*)wl, n4);
        n4 = ADIM * ADIM / 4;
        trunc_h<<<(n4 + 255) / 256, 256>>>((const float4*)J, (uint2*)jh, n4);
    }

    dim3 grid(ADIM / BN, BDIM / BM);  // (4, 128)

    // drive = x@W^T + b (fp32); sigma1 = tanh(drive) -> fp16 hi/lo
    drive_gemm<<<grid, 256, SMEM_DRIVE>>>(xh, xl, wh, wl, b, drv, sh0, sl0);

    // sigma2..sigma9 (8 mid steps, ping-pong)
    __half* H[2] = {sh0, sh1};
    __half* L[2] = {sl0, sl1};
    for (int i = 0; i < 8; i++) {
        settle_fp16<1><<<grid, 256, SMEM_SETTLE>>>(
            H[i & 1], L[i & 1], jh, drv, H[(i + 1) & 1], L[(i + 1) & 1], nullptr);
    }
    // sigma10 -> d_out (fp32)
    settle_fp16<2><<<grid, 256, SMEM_SETTLE>>>(sh0, sl0, jh, drv, nullptr, nullptr, out);
}

// round 10
// speedup vs baseline: 1.5662x; 1.5662x over previous
#include <cuda_runtime.h>
#include <cuda_bf16.h>
#include <cuda_fp16.h>
#include <cstdint>
#include <cstddef>

#define BDIM 16384
#define ADIM 512
#define MDIM 1024
#define INV_TAU 10.0f

// ---------- drive kernel geometry (bf16x3, BK=32, 64B rows) ----------
constexpr int BM = 128, BN = 128;
constexpr int PLANE_B = 128 * 64;          // 8 KB
constexpr int STAGE4_B = 4 * PLANE_B;      // A_hi A_lo B_hi B_lo
constexpr int SMEM_DRIVE = 2 * STAGE4_B;   // 64 KB
// ---------- settle kernel geometry (fp16 x1, BK=64, 128B rows) ----------
constexpr int PLANE128_B = 128 * 128;      // 16 KB
constexpr int STAGE2_B = 2 * PLANE128_B;   // A, B
constexpr int SMEM_SETTLE = 2 * STAGE2_B;  // 64 KB

// ---- device scratch (allocation-free rule: __device__ globals) ----
__device__ __align__(128) __nv_bfloat16 g_xh[(size_t)BDIM * MDIM];
__device__ __align__(128) __nv_bfloat16 g_xl[(size_t)BDIM * MDIM];
__device__ __align__(128) __nv_bfloat16 g_wh[(size_t)ADIM * MDIM];
__device__ __align__(128) __nv_bfloat16 g_wl[(size_t)ADIM * MDIM];
__device__ __align__(128) __half g_jh[(size_t)ADIM * ADIM];   // fp16 J
__device__ __align__(128) float g_drive[(size_t)BDIM * ADIM];
__device__ __align__(128) __half g_s0[(size_t)BDIM * ADIM];   // sigma fp16
__device__ __align__(128) __half g_s1[(size_t)BDIM * ADIM];

// ---- helpers ----
__device__ __forceinline__ void cp16(void* sdst, const void* gsrc) {
    uint32_t s = (uint32_t)__cvta_generic_to_shared(sdst);
    asm volatile("cp.async.cg.shared.global [%0], [%1], 16;\n" ::"r"(s), "l"(gsrc));
}

__device__ __forceinline__ void ldsm4(uint32_t* r, const void* p) {
    uint32_t a = (uint32_t)__cvta_generic_to_shared(p);
    asm volatile("ldmatrix.sync.aligned.m8n8.x4.shared.b16 {%0,%1,%2,%3}, [%4];\n"
                 : "=r"(r[0]), "=r"(r[1]), "=r"(r[2]), "=r"(r[3])
                 : "r"(a));
}

__device__ __forceinline__ void mma_bf16(float* c, const uint32_t* a, const uint32_t* b) {
    asm volatile(
        "mma.sync.aligned.m16n8k16.row.col.f32.bf16.bf16.f32 "
        "{%0,%1,%2,%3}, {%4,%5,%6,%7}, {%8,%9}, {%0,%1,%2,%3};\n"
        : "+f"(c[0]), "+f"(c[1]), "+f"(c[2]), "+f"(c[3])
        : "r"(a[0]), "r"(a[1]), "r"(a[2]), "r"(a[3]), "r"(b[0]), "r"(b[1]));
}

__device__ __forceinline__ void mma_fp16(float* c, const uint32_t* a, const uint32_t* b) {
    asm volatile(
        "mma.sync.aligned.m16n8k16.row.col.f32.f16.f16.f32 "
        "{%0,%1,%2,%3}, {%4,%5,%6,%7}, {%8,%9}, {%0,%1,%2,%3};\n"
        : "+f"(c[0]), "+f"(c[1]), "+f"(c[2]), "+f"(c[3])
        : "r"(a[0]), "r"(a[1]), "r"(a[2]), "r"(a[3]), "r"(b[0]), "r"(b[1]));
}

// 64B-row swizzle (drive kernel): rows of 32 elems x 2B, 4 chunks of 16B
__device__ __forceinline__ uint32_t swz(int r, int ch) {
    return (uint32_t)(r * 64 + ((ch ^ ((r >> 1) & 3)) << 4));
}
// 128B-row swizzle (settle kernel): rows of 64 elems x 2B, 8 chunks of 16B
__device__ __forceinline__ uint32_t swz128(int r, int ch) {
    return (uint32_t)(r * 128 + ((ch ^ (r & 7)) << 4));
}

__device__ __forceinline__ float fast_tanh(float x) {
    float e, r;
    asm("ex2.approx.f32 %0, %1;" : "=f"(e) : "f"(x * 2.8853901817f));  // 2*log2(e)*x
    asm("rcp.approx.f32 %0, %1;" : "=f"(r) : "f"(e + 1.0f));
    return fmaf(-2.0f, r, 1.0f);
}

// ---- split fp32 tensor into bf16 hi/lo planes (x, W) ----
__global__ void split_arr(const float4* __restrict__ src, uint2* __restrict__ hi,
                          uint2* __restrict__ lo, int n4) {
    int i = blockIdx.x * blockDim.x + threadIdx.x;
    if (i >= n4) return;
    float4 v = src[i];
    float f[4] = {v.x, v.y, v.z, v.w};
    uint32_t h[4], l[4];
#pragma unroll
    for (int k = 0; k < 4; k++) {
        __nv_bfloat16 hb = __float2bfloat16_rn(f[k]);
        __nv_bfloat16 lb = __float2bfloat16_rn(f[k] - __bfloat162float(hb));
        h[k] = (uint32_t)__bfloat16_as_ushort(hb);
        l[k] = (uint32_t)__bfloat16_as_ushort(lb);
    }
    hi[i] = make_uint2(h[0] | (h[1] << 16), h[2] | (h[3] << 16));
    lo[i] = make_uint2(l[0] | (l[1] << 16), l[2] | (l[3] << 16));
}

// ---- truncate fp32 -> fp16 (J) ----
__global__ void trunc_h(const float4* __restrict__ src, uint2* __restrict__ dst, int n4) {
    int i = blockIdx.x * blockDim.x + threadIdx.x;
    if (i >= n4) return;
    float4 v = src[i];
    __half2 a = __halves2half2(__float2half_rn(v.x), __float2half_rn(v.y));
    __half2 b = __halves2half2(__float2half_rn(v.z), __float2half_rn(v.w));
    dst[i] = make_uint2(*(uint32_t*)&a, *(uint32_t*)&b);
}

// ========== drive kernel: bf16x3, KD=1024 ==========
// drive = x@W^T + bias (fp32), sigma1 = tanh(drive) -> fp16
__global__ void __launch_bounds__(256, 2)
drive_gemm(const __nv_bfloat16* __restrict__ Ahi, const __nv_bfloat16* __restrict__ Alo,
           const __nv_bfloat16* __restrict__ Bhi, const __nv_bfloat16* __restrict__ Blo,
           const float* __restrict__ bias, float* __restrict__ of32,
           __half* __restrict__ osig) {
    constexpr int KD = MDIM;
    extern __shared__ char sm[];
    const int tid = threadIdx.x, lane = tid & 31, wid = tid >> 5;
    const int wm = wid & 3, wn = wid >> 2;
    const int rowBase = blockIdx.y * BM, colBase = blockIdx.x * BN;

    float acc[2][8][4];
#pragma unroll
    for (int mi = 0; mi < 2; mi++)
#pragma unroll
        for (int ni = 0; ni < 8; ni++)
#pragma unroll
            for (int q = 0; q < 4; q++) acc[mi][ni][q] = 0.f;

    uint32_t sA[2], gA[2], gB[2];
#pragma unroll
    for (int j = 0; j < 2; j++) {
        int c = tid + j * 256;
        int r = c >> 2, ch = c & 3;
        sA[j] = swz(r, ch);
        gA[j] = (uint32_t)(rowBase + r) * KD + ch * 8;
        gB[j] = (uint32_t)(colBase + r) * KD + ch * 8;
    }

    auto issue = [&](int kt, int s) {
        char* st = sm + s * STAGE4_B;
        const uint32_t kof = kt * 32;
#pragma unroll
        for (int j = 0; j < 2; j++) {
            cp16(st + sA[j], Ahi + gA[j] + kof);
            cp16(st + PLANE_B + sA[j], Alo + gA[j] + kof);
            cp16(st + 2 * PLANE_B + sA[j], Bhi + gB[j] + kof);
            cp16(st + 3 * PLANE_B + sA[j], Blo + gB[j] + kof);
        }
        asm volatile("cp.async.commit_group;\n");
    };

    const int arowl = lane & 15;
    const int browl = ((lane >> 4) << 3) + (lane & 7);
    uint32_t aOff[2][2], bOff[2][4];
#pragma unroll
    for (int k16 = 0; k16 < 2; k16++) {
        const int achunk = k16 * 2 + (lane >> 4);
        const int bchunk = k16 * 2 + ((lane >> 3) & 1);
#pragma unroll
        for (int mi = 0; mi < 2; mi++)
            aOff[k16][mi] = swz(wm * 32 + mi * 16 + arowl, achunk);
#pragma unroll
        for (int g = 0; g < 4; g++)
            bOff[k16][g] = swz(wn * 64 + g * 16 + browl, bchunk);
    }

    constexpr int KT = KD / 32;
    issue(0, 0);

    for (int kt = 0; kt < KT; kt++) {
        const int buf = kt & 1;
        if (kt + 1 < KT) {
            issue(kt + 1, buf ^ 1);
            asm volatile("cp.async.wait_group 1;\n");
        } else {
            asm volatile("cp.async.wait_group 0;\n");
        }
        __syncthreads();
        char* st = sm + buf * STAGE4_B;

#pragma unroll
        for (int k16 = 0; k16 < 2; k16++) {
            uint32_t ah[2][4], al[2][4], bb[4][4];
#pragma unroll
            for (int mi = 0; mi < 2; mi++) {
                ldsm4(ah[mi], st + aOff[k16][mi]);
                ldsm4(al[mi], st + PLANE_B + aOff[k16][mi]);
            }
#pragma unroll
            for (int g = 0; g < 4; g++)
                ldsm4(bb[g], st + 2 * PLANE_B + bOff[k16][g]);
#pragma unroll
            for (int ni = 0; ni < 8; ni++) {
                const uint32_t* b = &bb[ni >> 1][(ni & 1) * 2];
                mma_bf16(acc[0][ni], ah[0], b);
                mma_bf16(acc[1][ni], ah[1], b);
                mma_bf16(acc[0][ni], al[0], b);
                mma_bf16(acc[1][ni], al[1], b);
            }
#pragma unroll
            for (int g = 0; g < 4; g++)
                ldsm4(bb[g], st + 3 * PLANE_B + bOff[k16][g]);
#pragma unroll
            for (int ni = 0; ni < 8; ni++) {
                const uint32_t* b = &bb[ni >> 1][(ni & 1) * 2];
                mma_bf16(acc[0][ni], ah[0], b);
                mma_bf16(acc[1][ni], ah[1], b);
            }
        }
        __syncthreads();
    }

    const int lrow = lane >> 2, lcol = lane & 3;
#pragma unroll
    for (int mi = 0; mi < 2; mi++) {
#pragma unroll
        for (int ni = 0; ni < 8; ni++) {
            const int gr = rowBase + wm * 32 + mi * 16 + lrow;
            const int gc = colBase + wn * 64 + ni * 8 + lcol * 2;
            const uint32_t i0 = (uint32_t)gr * ADIM + gc;
            const uint32_t i1 = i0 + 8 * ADIM;
            const float b0 = bias[gc], b1 = bias[gc + 1];
            float v0 = acc[mi][ni][0] + b0, v1 = acc[mi][ni][1] + b1;
            float v2 = acc[mi][ni][2] + b0, v3 = acc[mi][ni][3] + b1;
            *(float2*)(of32 + i0) = make_float2(v0, v1);
            *(float2*)(of32 + i1) = make_float2(v2, v3);
            *(__half2*)(osig + i0) =
                __halves2half2(__float2half_rn(fast_tanh(v0)), __float2half_rn(fast_tanh(v1)));
            *(__half2*)(osig + i1) =
                __halves2half2(__float2half_rn(fast_tanh(v2)), __float2half_rn(fast_tanh(v3)));
        }
    }
}

// ========== settle kernel: fp16 single-pass, KD=512, BK=64 ==========
// s = tanh(drive + (sigma @ J^T) * INV_TAU)
// MODE 1: store fp16 sigma; MODE 2: store fp32 to of32
template <int MODE>
__global__ void __launch_bounds__(256, 2)
settle_fp16(const __half* __restrict__ Asig, const __half* __restrict__ Bj,
            const float* __restrict__ aux, __half* __restrict__ osig,
            float* __restrict__ of32) {
    constexpr int KD = ADIM;
    constexpr int BK = 64;
    extern __shared__ char sm[];
    const int tid = threadIdx.x, lane = tid & 31, wid = tid >> 5;
    const int wm = wid & 3, wn = wid >> 2;
    const int rowBase = blockIdx.y * BM, colBase = blockIdx.x * BN;

    float acc[2][8][4];
#pragma unroll
    for (int mi = 0; mi < 2; mi++)
#pragma unroll
        for (int ni = 0; ni < 8; ni++)
#pragma unroll
            for (int q = 0; q < 4; q++) acc[mi][ni][q] = 0.f;

    // producers: 1024 16B-chunks per plane, 4 per thread per plane
    uint32_t sO[4], gA[4], gB[4];
#pragma unroll
    for (int j = 0; j < 4; j++) {
        int c = tid + j * 256;
        int r = c >> 3, ch = c & 7;
        sO[j] = swz128(r, ch);
        gA[j] = (uint32_t)(rowBase + r) * KD + ch * 8;
        gB[j] = (uint32_t)(colBase + r) * KD + ch * 8;
    }

    auto issue = [&](int kt, int s) {
        char* st = sm + s * STAGE2_B;
        const uint32_t kof = kt * BK;
#pragma unroll
        for (int j = 0; j < 4; j++) {
            cp16(st + sO[j], Asig + gA[j] + kof);
            cp16(st + PLANE128_B + sO[j], Bj + gB[j] + kof);
        }
        asm volatile("cp.async.commit_group;\n");
    };

    const int arowl = lane & 15;
    const int browl = ((lane >> 4) << 3) + (lane & 7);
    uint32_t aOff[4][2], bOff[4][4];
#pragma unroll
    for (int k16 = 0; k16 < 4; k16++) {
        const int achunk = k16 * 2 + (lane >> 4);
        const int bchunk = k16 * 2 + ((lane >> 3) & 1);
#pragma unroll
        for (int mi = 0; mi < 2; mi++)
            aOff[k16][mi] = swz128(wm * 32 + mi * 16 + arowl, achunk);
#pragma unroll
        for (int g = 0; g < 4; g++)
            bOff[k16][g] = swz128(wn * 64 + g * 16 + browl, bchunk);
    }

    constexpr int KT = KD / BK;  // 8
    issue(0, 0);

    for (int kt = 0; kt < KT; kt++) {
        const int buf = kt & 1;
        if (kt + 1 < KT) {
            issue(kt + 1, buf ^ 1);
            asm volatile("cp.async.wait_group 1;\n");
        } else {
            asm volatile("cp.async.wait_group 0;\n");
        }
        __syncthreads();
        char* st = sm + buf * STAGE2_B;

#pragma unroll
        for (int k16 = 0; k16 < 4; k16++) {
            uint32_t ah[2][4], bb[4][4];
#pragma unroll
            for (int mi = 0; mi < 2; mi++)
                ldsm4(ah[mi], st + aOff[k16][mi]);
#pragma unroll
            for (int g = 0; g < 4; g++)
                ldsm4(bb[g], st + PLANE128_B + bOff[k16][g]);
#pragma unroll
            for (int ni = 0; ni < 8; ni++) {
                const uint32_t* b = &bb[ni >> 1][(ni & 1) * 2];
                mma_fp16(acc[0][ni], ah[0], b);
                mma_fp16(acc[1][ni], ah[1], b);
            }
        }
        __syncthreads();
    }

    const int lrow = lane >> 2, lcol = lane & 3;
#pragma unroll
    for (int mi = 0; mi < 2; mi++) {
#pragma unroll
        for (int ni = 0; ni < 8; ni++) {
            const int gr = rowBase + wm * 32 + mi * 16 + lrow;
            const int gc = colBase + wn * 64 + ni * 8 + lcol * 2;
            const uint32_t i0 = (uint32_t)gr * ADIM + gc;
            const uint32_t i1 = i0 + 8 * ADIM;
            const float2 d0 = *(const float2*)(aux + i0);
            const float2 d1 = *(const float2*)(aux + i1);
            float v0 = fast_tanh(fmaf(acc[mi][ni][0], INV_TAU, d0.x));
            float v1 = fast_tanh(fmaf(acc[mi][ni][1], INV_TAU, d0.y));
            float v2 = fast_tanh(fmaf(acc[mi][ni][2], INV_TAU, d1.x));
            float v3 = fast_tanh(fmaf(acc[mi][ni][3], INV_TAU, d1.y));
            if (MODE == 1) {
                *(__half2*)(osig + i0) = __halves2half2(__float2half_rn(v0), __float2half_rn(v1));
                *(__half2*)(osig + i1) = __halves2half2(__float2half_rn(v2), __float2half_rn(v3));
            } else {
                *(float2*)(of32 + i0) = make_float2(v0, v1);
                *(float2*)(of32 + i1) = make_float2(v2, v3);
            }
        }
    }
}

extern "C" void kernel_launch(void* const* d_in, const int* in_sizes, int n_in,
                              void* d_out, int out_size) {
    (void)in_sizes; (void)n_in; (void)out_size;
    const float* x = (const float*)d_in[0];  // [16384, 1024]
    const float* W = (const float*)d_in[1];  // [512, 1024]
    const float* b = (const float*)d_in[2];  // [512]
    const float* J = (const float*)d_in[3];  // [512, 512]
    float* out = (float*)d_out;              // [16384, 512]

    cudaFuncSetAttribute((const void*)drive_gemm,
                         cudaFuncAttributeMaxDynamicSharedMemorySize, SMEM_DRIVE);
    cudaFuncSetAttribute((const void*)settle_fp16<1>,
                         cudaFuncAttributeMaxDynamicSharedMemorySize, SMEM_SETTLE);
    cudaFuncSetAttribute((const void*)settle_fp16<2>,
                         cudaFuncAttributeMaxDynamicSharedMemorySize, SMEM_SETTLE);

    __nv_bfloat16 *xh, *xl, *wh, *wl;
    __half *jh, *s0, *s1;
    float* drv;
    cudaGetSymbolAddress((void**)&xh, g_xh);
    cudaGetSymbolAddress((void**)&xl, g_xl);
    cudaGetSymbolAddress((void**)&wh, g_wh);
    cudaGetSymbolAddress((void**)&wl, g_wl);
    cudaGetSymbolAddress((void**)&jh, g_jh);
    cudaGetSymbolAddress((void**)&s0, g_s0);
    cudaGetSymbolAddress((void**)&s1, g_s1);
    cudaGetSymbolAddress((void**)&drv, g_drive);

    {
        int n4 = BDIM * MDIM / 4;
        split_arr<<<(n4 + 255) / 256, 256>>>((const float4*)x, (uint2*)xh, (uint2*)xl, n4);
        n4 = ADIM * MDIM / 4;
        split_arr<<<(n4 + 255) / 256, 256>>>((const float4*)W, (uint2*)wh, (uint2*)wl, n4);
        n4 = ADIM * ADIM / 4;
        trunc_h<<<(n4 + 255) / 256, 256>>>((const float4*)J, (uint2*)jh, n4);
    }

    dim3 grid(ADIM / BN, BDIM / BM);  // (4, 128)

    // drive = x@W^T + b (fp32); sigma1 = tanh(drive) -> fp16
    drive_gemm<<<grid, 256, SMEM_DRIVE>>>(xh, xl, wh, wl, b, drv, s0);

    // sigma2..sigma9 (8 mid steps, ping-pong)
    __half* S[2] = {s0, s1};
    for (int i = 0; i < 8; i++) {
        settle_fp16<1><<<grid, 256, SMEM_SETTLE>>>(S[i & 1], jh, drv, S[(i + 1) & 1],
                                                   nullptr);
    }
    // sigma10 -> d_out (fp32)
    settle_fp16<2><<<grid, 256, SMEM_SETTLE>>>(s0, jh, drv, nullptr, out);
}

// round 11
// speedup vs baseline: 2.5518x; 1.6293x over previous
#include <cuda_runtime.h>
#include <cuda_bf16.h>
#include <cuda_fp16.h>
#include <cstdint>
#include <cstddef>

#define BDIM 16384
#define ADIM 512
#define MDIM 1024
#define INV_TAU 10.0f

constexpr int BM = 128, BN = 128;
// 128B-row planes (BK=64 fp16)
constexpr int PLANE128_B = 128 * 128;        // 16 KB
// drive: 3 planes (A_hi, A_lo, B) x 2 stages = 96 KB
constexpr int STAGE3_B = 3 * PLANE128_B;
constexpr int SMEM_DRIVE = 2 * STAGE3_B;
// settle: 2 planes x 3 stages = 96 KB
constexpr int STAGE2_B = 2 * PLANE128_B;
constexpr int SMEM_SETTLE = 3 * STAGE2_B;

// ---- device scratch (allocation-free rule: __device__ globals) ----
__device__ __align__(128) __half g_xh[(size_t)BDIM * MDIM];
__device__ __align__(128) __half g_xl[(size_t)BDIM * MDIM];
__device__ __align__(128) __half g_wh[(size_t)ADIM * MDIM];   // fp16 W
__device__ __align__(128) __half g_jh[(size_t)ADIM * ADIM];   // fp16 J
__device__ __align__(128) float g_drive[(size_t)BDIM * ADIM];
__device__ __align__(128) __half g_s0[(size_t)BDIM * ADIM];   // sigma fp16
__device__ __align__(128) __half g_s1[(size_t)BDIM * ADIM];

// ---- helpers ----
__device__ __forceinline__ void cp16(void* sdst, const void* gsrc) {
    uint32_t s = (uint32_t)__cvta_generic_to_shared(sdst);
    asm volatile("cp.async.cg.shared.global [%0], [%1], 16;\n" ::"r"(s), "l"(gsrc));
}

__device__ __forceinline__ void ldsm4(uint32_t* r, const void* p) {
    uint32_t a = (uint32_t)__cvta_generic_to_shared(p);
    asm volatile("ldmatrix.sync.aligned.m8n8.x4.shared.b16 {%0,%1,%2,%3}, [%4];\n"
                 : "=r"(r[0]), "=r"(r[1]), "=r"(r[2]), "=r"(r[3])
                 : "r"(a));
}

__device__ __forceinline__ void mma_fp16(float* c, const uint32_t* a, const uint32_t* b) {
    asm volatile(
        "mma.sync.aligned.m16n8k16.row.col.f32.f16.f16.f32 "
        "{%0,%1,%2,%3}, {%4,%5,%6,%7}, {%8,%9}, {%0,%1,%2,%3};\n"
        : "+f"(c[0]), "+f"(c[1]), "+f"(c[2]), "+f"(c[3])
        : "r"(a[0]), "r"(a[1]), "r"(a[2]), "r"(a[3]), "r"(b[0]), "r"(b[1]));
}

// 128B-row swizzle: rows of 64 fp16, 8 chunks of 16B
__device__ __forceinline__ uint32_t swz128(int r, int ch) {
    return (uint32_t)(r * 128 + ((ch ^ (r & 7)) << 4));
}

__device__ __forceinline__ float fast_tanh(float x) {
    float e, r;
    asm("ex2.approx.f32 %0, %1;" : "=f"(e) : "f"(x * 2.8853901817f));  // 2*log2(e)*x
    asm("rcp.approx.f32 %0, %1;" : "=f"(r) : "f"(e + 1.0f));
    return fmaf(-2.0f, r, 1.0f);
}

// ---- split fp32 -> fp16 hi/lo planes (x) ----
__global__ void split_h(const float4* __restrict__ src, uint2* __restrict__ hi,
                        uint2* __restrict__ lo, int n4) {
    int i = blockIdx.x * blockDim.x + threadIdx.x;
    if (i >= n4) return;
    float4 v = src[i];
    float f[4] = {v.x, v.y, v.z, v.w};
    uint16_t h[4], l[4];
#pragma unroll
    for (int k = 0; k < 4; k++) {
        __half hb = __float2half_rn(f[k]);
        __half lb = __float2half_rn(f[k] - __half2float(hb));
        h[k] = __half_as_ushort(hb);
        l[k] = __half_as_ushort(lb);
    }
    hi[i] = make_uint2((uint32_t)h[0] | ((uint32_t)h[1] << 16),
                       (uint32_t)h[2] | ((uint32_t)h[3] << 16));
    lo[i] = make_uint2((uint32_t)l[0] | ((uint32_t)l[1] << 16),
                       (uint32_t)l[2] | ((uint32_t)l[3] << 16));
}

// ---- truncate fp32 -> fp16 (W, J) ----
__global__ void trunc_h(const float4* __restrict__ src, uint2* __restrict__ dst, int n4) {
    int i = blockIdx.x * blockDim.x + threadIdx.x;
    if (i >= n4) return;
    float4 v = src[i];
    __half2 a = __halves2half2(__float2half_rn(v.x), __float2half_rn(v.y));
    __half2 b = __halves2half2(__float2half_rn(v.z), __float2half_rn(v.w));
    dst[i] = make_uint2(*(uint32_t*)&a, *(uint32_t*)&b);
}

// ========== drive kernel: fp16x2 (x exact, W truncated), KD=1024, BK=64 ==========
// drive = x@W^T + bias (fp32), sigma1 = tanh(drive) -> fp16
__global__ void __launch_bounds__(256, 2)
drive_gemm(const __half* __restrict__ Ahi, const __half* __restrict__ Alo,
           const __half* __restrict__ Bw, const float* __restrict__ bias,
           float* __restrict__ of32, __half* __restrict__ osig) {
    constexpr int KD = MDIM;
    constexpr int BK = 64;
    extern __shared__ char sm[];
    const int tid = threadIdx.x, lane = tid & 31, wid = tid >> 5;
    const int wm = wid & 3, wn = wid >> 2;
    const int rowBase = blockIdx.y * BM, colBase = blockIdx.x * BN;

    float acc[2][8][4];
#pragma unroll
    for (int mi = 0; mi < 2; mi++)
#pragma unroll
        for (int ni = 0; ni < 8; ni++)
#pragma unroll
            for (int q = 0; q < 4; q++) acc[mi][ni][q] = 0.f;

    uint32_t sO[4], gA[4], gB[4];
#pragma unroll
    for (int j = 0; j < 4; j++) {
        int c = tid + j * 256;
        int r = c >> 3, ch = c & 7;
        sO[j] = swz128(r, ch);
        gA[j] = (uint32_t)(rowBase + r) * KD + ch * 8;
        gB[j] = (uint32_t)(colBase + r) * KD + ch * 8;
    }

    auto issue = [&](int kt, int s) {
        char* st = sm + s * STAGE3_B;
        const uint32_t kof = kt * BK;
#pragma unroll
        for (int j = 0; j < 4; j++) {
            cp16(st + sO[j], Ahi + gA[j] + kof);
            cp16(st + PLANE128_B + sO[j], Alo + gA[j] + kof);
            cp16(st + 2 * PLANE128_B + sO[j], Bw + gB[j] + kof);
        }
        asm volatile("cp.async.commit_group;\n");
    };

    const int arowl = lane & 15;
    const int browl = ((lane >> 4) << 3) + (lane & 7);
    uint32_t aOff[4][2], bOff[4][4];
#pragma unroll
    for (int k16 = 0; k16 < 4; k16++) {
        const int achunk = k16 * 2 + (lane >> 4);
        const int bchunk = k16 * 2 + ((lane >> 3) & 1);
#pragma unroll
        for (int mi = 0; mi < 2; mi++)
            aOff[k16][mi] = swz128(wm * 32 + mi * 16 + arowl, achunk);
#pragma unroll
        for (int g = 0; g < 4; g++)
            bOff[k16][g] = swz128(wn * 64 + g * 16 + browl, bchunk);
    }

    constexpr int KT = KD / BK;  // 16
    issue(0, 0);

    for (int kt = 0; kt < KT; kt++) {
        const int buf = kt & 1;
        if (kt + 1 < KT) {
            issue(kt + 1, buf ^ 1);
            asm volatile("cp.async.wait_group 1;\n");
        } else {
            asm volatile("cp.async.wait_group 0;\n");
        }
        __syncthreads();
        char* st = sm + buf * STAGE3_B;

#pragma unroll
        for (int k16 = 0; k16 < 4; k16++) {
            uint32_t ah[2][4], al[2][4], bb[4][4];
#pragma unroll
            for (int mi = 0; mi < 2; mi++) {
                ldsm4(ah[mi], st + aOff[k16][mi]);
                ldsm4(al[mi], st + PLANE128_B + aOff[k16][mi]);
            }
#pragma unroll
            for (int g = 0; g < 4; g++)
                ldsm4(bb[g], st + 2 * PLANE128_B + bOff[k16][g]);
#pragma unroll
            for (int ni = 0; ni < 8; ni++) {
                const uint32_t* b = &bb[ni >> 1][(ni & 1) * 2];
                mma_fp16(acc[0][ni], ah[0], b);
                mma_fp16(acc[1][ni], ah[1], b);
                mma_fp16(acc[0][ni], al[0], b);
                mma_fp16(acc[1][ni], al[1], b);
            }
        }
        __syncthreads();
    }

    const int lrow = lane >> 2, lcol = lane & 3;
#pragma unroll
    for (int mi = 0; mi < 2; mi++) {
#pragma unroll
        for (int ni = 0; ni < 8; ni++) {
            const int gr = rowBase + wm * 32 + mi * 16 + lrow;
            const int gc = colBase + wn * 64 + ni * 8 + lcol * 2;
            const uint32_t i0 = (uint32_t)gr * ADIM + gc;
            const uint32_t i1 = i0 + 8 * ADIM;
            const float b0 = bias[gc], b1 = bias[gc + 1];
            float v0 = acc[mi][ni][0] + b0, v1 = acc[mi][ni][1] + b1;
            float v2 = acc[mi][ni][2] + b0, v3 = acc[mi][ni][3] + b1;
            *(float2*)(of32 + i0) = make_float2(v0, v1);
            *(float2*)(of32 + i1) = make_float2(v2, v3);
            *(__half2*)(osig + i0) =
                __halves2half2(__float2half_rn(fast_tanh(v0)), __float2half_rn(fast_tanh(v1)));
            *(__half2*)(osig + i1) =
                __halves2half2(__float2half_rn(fast_tanh(v2)), __float2half_rn(fast_tanh(v3)));
        }
    }
}

// ========== settle kernel: fp16 single-pass, KD=512, BK=64, 3-stage ==========
// s = tanh(drive + (sigma @ J^T) * INV_TAU)
// MODE 1: store fp16 sigma; MODE 2: store fp32 to of32
template <int MODE>
__global__ void __launch_bounds__(256, 2)
settle_fp16(const __half* __restrict__ Asig, const __half* __restrict__ Bj,
            const float* __restrict__ aux, __half* __restrict__ osig,
            float* __restrict__ of32) {
    constexpr int KD = ADIM;
    constexpr int BK = 64;
    constexpr int NS = 3;
    extern __shared__ char sm[];
    const int tid = threadIdx.x, lane = tid & 31, wid = tid >> 5;
    const int wm = wid & 3, wn = wid >> 2;
    const int rowBase = blockIdx.y * BM, colBase = blockIdx.x * BN;

    float acc[2][8][4];
#pragma unroll
    for (int mi = 0; mi < 2; mi++)
#pragma unroll
        for (int ni = 0; ni < 8; ni++)
#pragma unroll
            for (int q = 0; q < 4; q++) acc[mi][ni][q] = 0.f;

    uint32_t sO[4], gA[4], gB[4];
#pragma unroll
    for (int j = 0; j < 4; j++) {
        int c = tid + j * 256;
        int r = c >> 3, ch = c & 7;
        sO[j] = swz128(r, ch);
        gA[j] = (uint32_t)(rowBase + r) * KD + ch * 8;
        gB[j] = (uint32_t)(colBase + r) * KD + ch * 8;
    }

    auto issue = [&](int kt, int s) {
        char* st = sm + s * STAGE2_B;
        const uint32_t kof = kt * BK;
#pragma unroll
        for (int j = 0; j < 4; j++) {
            cp16(st + sO[j], Asig + gA[j] + kof);
            cp16(st + PLANE128_B + sO[j], Bj + gB[j] + kof);
        }
        asm volatile("cp.async.commit_group;\n");
    };

    const int arowl = lane & 15;
    const int browl = ((lane >> 4) << 3) + (lane & 7);
    uint32_t aOff[4][2], bOff[4][4];
#pragma unroll
    for (int k16 = 0; k16 < 4; k16++) {
        const int achunk = k16 * 2 + (lane >> 4);
        const int bchunk = k16 * 2 + ((lane >> 3) & 1);
#pragma unroll
        for (int mi = 0; mi < 2; mi++)
            aOff[k16][mi] = swz128(wm * 32 + mi * 16 + arowl, achunk);
#pragma unroll
        for (int g = 0; g < 4; g++)
            bOff[k16][g] = swz128(wn * 64 + g * 16 + browl, bchunk);
    }

    constexpr int KT = KD / BK;  // 8
    issue(0, 0);
    issue(1, 1);

    for (int kt = 0; kt < KT; kt++) {
        const int buf = kt % NS;
        if (kt + 2 < KT) {
            issue(kt + 2, (kt + 2) % NS);
            asm volatile("cp.async.wait_group 2;\n");
        } else if (kt + 1 < KT) {
            asm volatile("cp.async.wait_group 1;\n");
        } else {
            asm volatile("cp.async.wait_group 0;\n");
        }
        __syncthreads();
        char* st = sm + buf * STAGE2_B;

#pragma unroll
        for (int k16 = 0; k16 < 4; k16++) {
            uint32_t ah[2][4], bb[4][4];
#pragma unroll
            for (int mi = 0; mi < 2; mi++)
                ldsm4(ah[mi], st + aOff[k16][mi]);
#pragma unroll
            for (int g = 0; g < 4; g++)
                ldsm4(bb[g], st + PLANE128_B + bOff[k16][g]);
#pragma unroll
            for (int ni = 0; ni < 8; ni++) {
                const uint32_t* b = &bb[ni >> 1][(ni & 1) * 2];
                mma_fp16(acc[0][ni], ah[0], b);
                mma_fp16(acc[1][ni], ah[1], b);
            }
        }
        __syncthreads();
    }

    const int lrow = lane >> 2, lcol = lane & 3;
#pragma unroll
    for (int mi = 0; mi < 2; mi++) {
#pragma unroll
        for (int ni = 0; ni < 8; ni++) {
            const int gr = rowBase + wm * 32 + mi * 16 + lrow;
            const int gc = colBase + wn * 64 + ni * 8 + lcol * 2;
            const uint32_t i0 = (uint32_t)gr * ADIM + gc;
            const uint32_t i1 = i0 + 8 * ADIM;
            const float2 d0 = *(const float2*)(aux + i0);
            const float2 d1 = *(const float2*)(aux + i1);
            float v0 = fast_tanh(fmaf(acc[mi][ni][0], INV_TAU, d0.x));
            float v1 = fast_tanh(fmaf(acc[mi][ni][1], INV_TAU, d0.y));
            float v2 = fast_tanh(fmaf(acc[mi][ni][2], INV_TAU, d1.x));
            float v3 = fast_tanh(fmaf(acc[mi][ni][3], INV_TAU, d1.y));
            if (MODE == 1) {
                *(__half2*)(osig + i0) = __halves2half2(__float2half_rn(v0), __float2half_rn(v1));
                *(__half2*)(osig + i1) = __halves2half2(__float2half_rn(v2), __float2half_rn(v3));
            } else {
                *(float2*)(of32 + i0) = make_float2(v0, v1);
                *(float2*)(of32 + i1) = make_float2(v2, v3);
            }
        }
    }
}

extern "C" void kernel_launch(void* const* d_in, const int* in_sizes, int n_in,
                              void* d_out, int out_size) {
    (void)in_sizes; (void)n_in; (void)out_size;
    const float* x = (const float*)d_in[0];  // [16384, 1024]
    const float* W = (const float*)d_in[1];  // [512, 1024]
    const float* b = (const float*)d_in[2];  // [512]
    const float* J = (const float*)d_in[3];  // [512, 512]
    float* out = (float*)d_out;              // [16384, 512]

    cudaFuncSetAttribute((const void*)drive_gemm,
                         cudaFuncAttributeMaxDynamicSharedMemorySize, SMEM_DRIVE);
    cudaFuncSetAttribute((const void*)settle_fp16<1>,
                         cudaFuncAttributeMaxDynamicSharedMemorySize, SMEM_SETTLE);
    cudaFuncSetAttribute((const void*)settle_fp16<2>,
                         cudaFuncAttributeMaxDynamicSharedMemorySize, SMEM_SETTLE);

    __half *xh, *xl, *wh, *jh, *s0, *s1;
    float* drv;
    cudaGetSymbolAddress((void**)&xh, g_xh);
    cudaGetSymbolAddress((void**)&xl, g_xl);
    cudaGetSymbolAddress((void**)&wh, g_wh);
    cudaGetSymbolAddress((void**)&jh, g_jh);
    cudaGetSymbolAddress((void**)&s0, g_s0);
    cudaGetSymbolAddress((void**)&s1, g_s1);
    cudaGetSymbolAddress((void**)&drv, g_drive);

    {
        int n4 = BDIM * MDIM / 4;
        split_h<<<(n4 + 255) / 256, 256>>>((const float4*)x, (uint2*)xh, (uint2*)xl, n4);
        n4 = ADIM * MDIM / 4;
        trunc_h<<<(n4 + 255) / 256, 256>>>((const float4*)W, (uint2*)wh, n4);
        n4 = ADIM * ADIM / 4;
        trunc_h<<<(n4 + 255) / 256, 256>>>((const float4*)J, (uint2*)jh, n4);
    }

    dim3 grid(ADIM / BN, BDIM / BM);  // (4, 128)

    // drive = x@W^T + b (fp32); sigma1 = tanh(drive) -> fp16
    drive_gemm<<<grid, 256, SMEM_DRIVE>>>(xh, xl, wh, b, drv, s0);

    // sigma2..sigma9 (8 mid steps, ping-pong)
    __half* S[2] = {s0, s1};
    for (int i = 0; i < 8; i++) {
        settle_fp16<1><<<grid, 256, SMEM_SETTLE>>>(S[i & 1], jh, drv, S[(i + 1) & 1],
                                                   nullptr);
    }
    // sigma10 -> d_out (fp32)
    settle_fp16<2><<<grid, 256, SMEM_SETTLE>>>(s0, jh, drv, nullptr, out);
}